// round 15
// baseline (speedup 1.0000x reference)
#include <cuda_runtime.h>
#include <cstdint>

#define NB 4
#define NS 512
#define ND 768
#define NL 64

#define BM 64
#define BN 64
#define BK 32
#define LT 4
#define NCH (ND / BK)   // 24
#define NST 4           // cp.async pipeline stages

// SMEM layout (bytes), dynamic:
//   stage s (s=0..3): A[64][36] floats at s*STAGE_B, B[64][36] at s*STAGE_B + B_OFF
//   Upk (packed, scaled U) at U_OFF: 96 k-groups * 4 labels * 8 floats = 3072 floats
#define TSTR 36
#define TILE_B (BM * TSTR * 4)        // 9216
#define B_OFF  TILE_B                 // 9216
#define STAGE_B (2 * TILE_B)          // 18432
#define U_OFF  (NST * STAGE_B)        // 73728
#define SMEM_BYTES (U_OFF + LT * ND * 4)   // 86016

// Truncation-bias cancellation: HMMA truncates fp32->tf32 (mean rel loss ~2^-11
// per operand); scaling U by (1+2^-10) cancels the combined A+B bias.
#define U_CORR 1.0009765625f

// Scratch for the rank-1 epilogue terms.
__device__ float g_rowadd[NB * NL * NS];  // head . Wh + bias
__device__ float g_coladd[NB * NL * NS];  // dep  . Wd

__device__ __forceinline__ uint32_t smem_u32(const void* p) {
    uint32_t a;
    asm("{ .reg .u64 t; cvta.to.shared.u64 t, %1; cvt.u32.u64 %0, t; }"
        : "=r"(a) : "l"(p));
    return a;
}

__device__ __forceinline__ void mma_tf32(float* c, const uint32_t* a,
                                         uint32_t b0, uint32_t b1) {
    asm volatile(
        "mma.sync.aligned.m16n8k8.row.col.f32.tf32.tf32.f32 "
        "{%0,%1,%2,%3}, {%4,%5,%6,%7}, {%8,%9}, {%0,%1,%2,%3};"
        : "+f"(c[0]), "+f"(c[1]), "+f"(c[2]), "+f"(c[3])
        : "r"(a[0]), "r"(a[1]), "r"(a[2]), "r"(a[3]), "r"(b0), "r"(b1));
}

#define LDSM4(r, addr)                                                        \
    asm volatile("ldmatrix.sync.aligned.m8n8.x4.shared.b16 {%0,%1,%2,%3}, [%4];" \
                 : "=r"((r)[0]), "=r"((r)[1]), "=r"((r)[2]), "=r"((r)[3])     \
                 : "r"(addr))

#define CP16(dst, src)                                                        \
    asm volatile("cp.async.ca.shared.global [%0], [%1], 16;"                  \
                 :: "r"(dst), "l"(src))
#define CP_COMMIT() asm volatile("cp.async.commit_group;" ::: "memory")
#define CP_WAIT2()  asm volatile("cp.async.wait_group 2;" ::: "memory")
#define CP_WAIT0()  asm volatile("cp.async.wait_group 0;" ::: "memory")

// ---------------------------------------------------------------------------
// Stage 1 (unchanged, known-good): rank-1 epilogue terms.
// ---------------------------------------------------------------------------
__global__ void __launch_bounds__(256) stage1_kernel(
    const float* __restrict__ head, const float* __restrict__ dep,
    const float* __restrict__ W, const float* __restrict__ bias)
{
    __shared__ float Xs[32][36];
    __shared__ float Ws[64][33];

    const int which = blockIdx.y;
    const float* X = which ? dep : head;
    const int b  = blockIdx.x >> 4;
    const int i0 = (blockIdx.x & 15) * 32;

    const int t  = threadIdx.x;
    const int l  = t & 63;
    const int rg = t >> 6;
    const int fr = t >> 3;
    const int fc = (t & 7) * 4;

    float acc[8];
#pragma unroll
    for (int j = 0; j < 8; j++) acc[j] = 0.f;

    for (int k0 = 0; k0 < ND; k0 += 32) {
        __syncthreads();
        float4 xv = *(const float4*)&X[((size_t)(b * NS + i0 + fr)) * ND + k0 + fc];
        *(float4*)&Xs[fr][fc] = xv;
        float4 w0 = *(const float4*)&W[(size_t)fr * (2 * ND) + which * ND + k0 + fc];
        float4 w1 = *(const float4*)&W[(size_t)(fr + 32) * (2 * ND) + which * ND + k0 + fc];
        Ws[fr][fc + 0] = w0.x; Ws[fr][fc + 1] = w0.y;
        Ws[fr][fc + 2] = w0.z; Ws[fr][fc + 3] = w0.w;
        Ws[fr + 32][fc + 0] = w1.x; Ws[fr + 32][fc + 1] = w1.y;
        Ws[fr + 32][fc + 2] = w1.z; Ws[fr + 32][fc + 3] = w1.w;
        __syncthreads();
#pragma unroll
        for (int kk = 0; kk < 32; kk++) {
            float wv = Ws[l][kk];
#pragma unroll
            for (int j = 0; j < 8; j++)
                acc[j] += Xs[rg + 4 * j][kk] * wv;
        }
    }

    const float bb = which ? 0.f : bias[l];
    float* dst = which ? g_coladd : g_rowadd;
#pragma unroll
    for (int j = 0; j < 8; j++)
        dst[((size_t)(b * NL + l)) * NS + i0 + rg + 4 * j] = acc[j] + bb;
}

// ---------------------------------------------------------------------------
// Main kernel: tf32 mma.sync + ldmatrix fragment loads + cp.async 4-stage
// pipeline. Raw fp32 tiles in SMEM (HW truncates to tf32; bias cancelled via
// U_CORR on U). B fragments scaled by U[l] in registers (R6 scheme).
// grid = (8, 8, 64), block = 256 (8 warps, 2x4 warp grid, 32x16 tile/label).
// ---------------------------------------------------------------------------
__global__ void __launch_bounds__(256, 2) biaffine_main_kernel(
    const float* __restrict__ head, const float* __restrict__ dep,
    const float* __restrict__ U, float* __restrict__ out)
{
    extern __shared__ float smf[];
    const uint32_t smb = smem_u32(smf);
    float* Upk = smf + U_OFF / 4;

    const int o0 = blockIdx.x * BN;
    const int i0 = blockIdx.y * BM;
    const int b  = blockIdx.z >> 4;
    const int l0 = (blockIdx.z & 15) * LT;

    const int t    = threadIdx.x;
    const int warp = t >> 5;
    const int lane = t & 31;
    const int wm   = warp >> 2;   // 0..1
    const int wn   = warp & 3;    // 0..3
    const int tig  = lane & 3;    // 0..3

    float acc[LT][2][2][4];
#pragma unroll
    for (int l = 0; l < LT; l++)
#pragma unroll
        for (int mt = 0; mt < 2; mt++)
#pragma unroll
            for (int nt = 0; nt < 2; nt++)
#pragma unroll
                for (int q = 0; q < 4; q++) acc[l][mt][nt][q] = 0.f;

    // ---- U preload: scale by U_CORR and pack as [kgroup][label][tig][2] ----
    // Upk[g*32 + l*8 + c2*2 + h] = U[l0+l][g*8 + c2 + 4h] * U_CORR
#pragma unroll
    for (int j = 0; j < 12; j++) {
        const int p  = t + 256 * j;        // 0..3071
        const int l  = p / ND;
        const int kk = p - l * ND;
        const int g  = kk >> 3;
        const int c  = kk & 7;
        Upk[g * 32 + l * 8 + (c & 3) * 2 + (c >> 2)] =
            __ldg(U + (size_t)l0 * ND + p) * U_CORR;
    }

    // ---- cp.async fill geometry: fr = row 0..31, q = float4 col 0..7 ----
    const int fr = t >> 3;
    const int q  = t & 7;
    const float* hp = &head[((size_t)(b * NS + i0 + fr)) * ND + q * 4];
    const float* dp = &dep [((size_t)(b * NS + o0 + fr)) * ND + q * 4];
    const uint32_t dA0 = (uint32_t)((fr * TSTR + q * 4) * 4);
    const uint32_t dA1 = (uint32_t)(((fr + 32) * TSTR + q * 4) * 4);

#define ISSUE_CHUNK(c)                                                        \
    do {                                                                      \
        const uint32_t sb = smb + ((c) & 3) * STAGE_B;                        \
        const float* hsrc = hp + (c) * BK;                                    \
        const float* dsrc = dp + (c) * BK;                                    \
        CP16(sb + dA0, hsrc);                                                 \
        CP16(sb + dA1, hsrc + 32 * ND);                                       \
        CP16(sb + B_OFF + dA0, dsrc);                                         \
        CP16(sb + B_OFF + dA1, dsrc + 32 * ND);                               \
        CP_COMMIT();                                                          \
    } while (0)

    ISSUE_CHUNK(0);
    ISSUE_CHUNK(1);
    ISSUE_CHUNK(2);

    // ---- ldmatrix per-lane addresses (bytes, within stage) ----
    // A matrices: row = wm*32 [+ mt*16] + (lane&7) + ((lane>>3)&1)*8,
    //             col = kc + ((lane>>4)&1)*4
    const uint32_t aLane = smb +
        (uint32_t)(((wm * 32 + (lane & 7) + ((lane >> 3) & 1) * 8) * TSTR +
                    ((lane >> 4) & 1) * 4) * 4);
    // B matrices: row = wn*16 + (lane&7) + ((lane>>4)&1)*8, col = kc + ((lane>>3)&1)*4
    const uint32_t bLane = smb + B_OFF +
        (uint32_t)(((wn * 16 + (lane & 7) + ((lane >> 4) & 1) * 8) * TSTR +
                    ((lane >> 3) & 1) * 4) * 4);

    const float* uBase = Upk + tig * 2;

    for (int ch = 0; ch < NCH; ch++) {
        if (ch < NCH - 2) CP_WAIT2(); else CP_WAIT0();
        __syncthreads();

        // prefetch 3 chunks ahead (stage just freed by the barrier above)
        if (ch + 3 < NCH) ISSUE_CHUNK(ch + 3);

        const uint32_t stg = (uint32_t)((ch & 3) * STAGE_B);
        const uint32_t aA = aLane + stg;
        const uint32_t bA = bLane + stg;
        const float* uc = uBase + ch * 128;   // (ch*4 kgroups)*32 floats

#pragma unroll
        for (int kt = 0; kt < 4; kt++) {
            uint32_t a0[4], a1[4], br[4];
            LDSM4(a0, aA + kt * 32);                  // mt=0: rows wm*32..+15
            LDSM4(a1, aA + 16 * TSTR * 4 + kt * 32);  // mt=1: rows +16..31
            LDSM4(br, bA + kt * 32);                  // both nt, cols kc/kc+4

#pragma unroll
            for (int l = 0; l < LT; l++) {
                const float2 u = *(const float2*)(uc + kt * 32 + l * 8);
                {
                    const uint32_t b0 = __float_as_uint(__uint_as_float(br[0]) * u.x);
                    const uint32_t b1 = __float_as_uint(__uint_as_float(br[1]) * u.y);
                    mma_tf32(acc[l][0][0], a0, b0, b1);
                    mma_tf32(acc[l][1][0], a1, b0, b1);
                }
                {
                    const uint32_t b0 = __float_as_uint(__uint_as_float(br[2]) * u.x);
                    const uint32_t b1 = __float_as_uint(__uint_as_float(br[3]) * u.y);
                    mma_tf32(acc[l][0][1], a0, b0, b1);
                    mma_tf32(acc[l][1][1], a1, b0, b1);
                }
            }
        }
    }

    // Epilogue: + rowadd[b,l,i] + coladd[b,l,o]  (bias folded into rowadd).
    const int gid = lane >> 2;
#pragma unroll
    for (int l = 0; l < LT; l++) {
        const int lg = l0 + l;
        const float* radd = &g_rowadd[((size_t)(b * NL + lg)) * NS + i0];
        const float* cadd = &g_coladd[((size_t)(b * NL + lg)) * NS + o0];
        float* op = out + (((size_t)(b * NL + lg)) * NS + i0) * NS + o0;
#pragma unroll
        for (int mt = 0; mt < 2; mt++) {
            const int r0 = wm * 32 + mt * 16 + gid;
            const float ra0 = radd[r0];
            const float ra1 = radd[r0 + 8];
#pragma unroll
            for (int nt = 0; nt < 2; nt++) {
                const int c = wn * 16 + nt * 8 + 2 * tig;
                const float2 ca = *(const float2*)&cadd[c];
                float2 v0, v1;
                v0.x = acc[l][mt][nt][0] + ra0 + ca.x;
                v0.y = acc[l][mt][nt][1] + ra0 + ca.y;
                v1.x = acc[l][mt][nt][2] + ra1 + ca.x;
                v1.y = acc[l][mt][nt][3] + ra1 + ca.y;
                *(float2*)&op[(size_t)r0 * NS + c]       = v0;
                *(float2*)&op[(size_t)(r0 + 8) * NS + c] = v1;
            }
        }
    }
}

extern "C" void kernel_launch(void* const* d_in, const int* in_sizes, int n_in,
                              void* d_out, int out_size) {
    const float* head = (const float*)d_in[0];
    const float* dep  = (const float*)d_in[1];
    const float* U    = (const float*)d_in[2];
    const float* W    = (const float*)d_in[3];
    const float* bias = (const float*)d_in[4];
    float* out = (float*)d_out;

    cudaFuncSetAttribute(biaffine_main_kernel,
                         cudaFuncAttributeMaxDynamicSharedMemorySize, SMEM_BYTES);

    stage1_kernel<<<dim3(NB * (NS / 32), 2), 256>>>(head, dep, W, bias);
    biaffine_main_kernel<<<dim3(NS / BN, NS / BM, NB * (NL / LT)), 256, SMEM_BYTES>>>(
        head, dep, U, out);
}

// round 16
// speedup vs baseline: 1.4792x; 1.4792x over previous
#include <cuda_runtime.h>
#include <cstdint>

#define NB 4
#define NS 512
#define ND 768
#define NL 64

#define BM 64
#define BN 64
#define BK 64
#define LT 4
#define NCH (ND / BK)   // 12

// SMEM floats: As[2][64][68], Bs[2][64][68], Us[4][768]
#define ST_STRIDE 68
#define ST_FLOATS (BM * ST_STRIDE)        // 4352 per stage per matrix
#define OFF_B (2 * ST_FLOATS)             // 8704
#define OFF_U (4 * ST_FLOATS)             // 17408
#define SMEM_BYTES ((4 * ST_FLOATS + LT * ND) * 4)   // 81920

// Scratch for the rank-1 epilogue terms.
__device__ float g_rowadd[NB * NL * NS];  // head . Wh + bias
__device__ float g_coladd[NB * NL * NS];  // dep  . Wd

__device__ __forceinline__ uint32_t f2tf(float x) {
    uint32_t r;
    asm("cvt.rna.tf32.f32 %0, %1;" : "=r"(r) : "f"(x));
    return r;
}

__device__ __forceinline__ void mma_tf32(float* c, const uint32_t* a,
                                         uint32_t b0, uint32_t b1) {
    asm volatile(
        "mma.sync.aligned.m16n8k8.row.col.f32.tf32.tf32.f32 "
        "{%0,%1,%2,%3}, {%4,%5,%6,%7}, {%8,%9}, {%0,%1,%2,%3};"
        : "+f"(c[0]), "+f"(c[1]), "+f"(c[2]), "+f"(c[3])
        : "r"(a[0]), "r"(a[1]), "r"(a[2]), "r"(a[3]), "r"(b0), "r"(b1));
}

// ---------------------------------------------------------------------------
// Stage 1 (unchanged, known-good): rank-1 epilogue terms.
// ---------------------------------------------------------------------------
__global__ void __launch_bounds__(256) stage1_kernel(
    const float* __restrict__ head, const float* __restrict__ dep,
    const float* __restrict__ W, const float* __restrict__ bias)
{
    __shared__ float Xs[32][36];
    __shared__ float Ws[64][33];

    const int which = blockIdx.y;
    const float* X = which ? dep : head;
    const int b  = blockIdx.x >> 4;
    const int i0 = (blockIdx.x & 15) * 32;

    const int t  = threadIdx.x;
    const int l  = t & 63;
    const int rg = t >> 6;
    const int fr = t >> 3;
    const int fc = (t & 7) * 4;

    float acc[8];
#pragma unroll
    for (int j = 0; j < 8; j++) acc[j] = 0.f;

    for (int k0 = 0; k0 < ND; k0 += 32) {
        __syncthreads();
        float4 xv = *(const float4*)&X[((size_t)(b * NS + i0 + fr)) * ND + k0 + fc];
        *(float4*)&Xs[fr][fc] = xv;
        float4 w0 = *(const float4*)&W[(size_t)fr * (2 * ND) + which * ND + k0 + fc];
        float4 w1 = *(const float4*)&W[(size_t)(fr + 32) * (2 * ND) + which * ND + k0 + fc];
        Ws[fr][fc + 0] = w0.x; Ws[fr][fc + 1] = w0.y;
        Ws[fr][fc + 2] = w0.z; Ws[fr][fc + 3] = w0.w;
        Ws[fr + 32][fc + 0] = w1.x; Ws[fr + 32][fc + 1] = w1.y;
        Ws[fr + 32][fc + 2] = w1.z; Ws[fr + 32][fc + 3] = w1.w;
        __syncthreads();
#pragma unroll
        for (int kk = 0; kk < 32; kk++) {
            float wv = Ws[l][kk];
#pragma unroll
            for (int j = 0; j < 8; j++)
                acc[j] += Xs[rg + 4 * j][kk] * wv;
        }
    }

    const float bb = which ? 0.f : bias[l];
    float* dst = which ? g_coladd : g_rowadd;
#pragma unroll
    for (int j = 0; j < 8; j++)
        dst[((size_t)(b * NL + l)) * NS + i0 + rg + 4 * j] = acc[j] + bb;
}

// ---------------------------------------------------------------------------
// Main kernel: R6 structure with BK=64 (half the barriers). Per chunk:
//   LDG half0(next) -> kt0-3 MMAs -> STS half0 -> LDG half1 -> kt4-7 MMAs
//   -> STS half1 -> one __syncthreads.
// Fragment LDS and fill STS keep R6's conflict-free pattern (68 = 36 mod 32).
// grid = (8, 8, 64), block = 256 (8 warps, 2x4 warp grid, 32x16 warp tile).
// ---------------------------------------------------------------------------
__global__ void __launch_bounds__(256, 2) biaffine_main_kernel(
    const float* __restrict__ head, const float* __restrict__ dep,
    const float* __restrict__ U, float* __restrict__ out)
{
    extern __shared__ float smf[];
    float* AsBase = smf;            // [2][64][68]
    float* BsBase = smf + OFF_B;    // [2][64][68]
    float* Us     = smf + OFF_U;    // [4][768]

    const int o0 = blockIdx.x * BN;
    const int i0 = blockIdx.y * BM;
    const int b  = blockIdx.z >> 4;
    const int l0 = (blockIdx.z & 15) * LT;

    const int t    = threadIdx.x;
    const int warp = t >> 5;
    const int lane = t & 31;
    const int wm   = warp >> 2;   // 0..1
    const int wn   = warp & 3;    // 0..3
    const int gid  = lane >> 2;   // 0..7
    const int tig  = lane & 3;    // 0..3

    float acc[LT][2][2][4];
#pragma unroll
    for (int l = 0; l < LT; l++)
#pragma unroll
        for (int mt = 0; mt < 2; mt++)
#pragma unroll
            for (int nt = 0; nt < 2; nt++)
#pragma unroll
                for (int q = 0; q < 4; q++) acc[l][mt][nt][q] = 0.f;

    // Preload the 4 U rows (contiguous 3072 floats) into SMEM once.
    {
        const float4* usrc = (const float4*)(U + (size_t)l0 * ND);
        float4* udst = (float4*)Us;
#pragma unroll
        for (int j = 0; j < 3; j++)
            udst[t + 256 * j] = __ldg(&usrc[t + 256 * j]);
    }

    const int fr = t >> 3;        // 0..31
    const int fc = (t & 7) * 4;   // 0..28
    const float* hp = &head[((size_t)(b * NS + i0 + fr)) * ND + fc];
    const float* dp = &dep [((size_t)(b * NS + o0 + fr)) * ND + fc];

#define CVT_STS(dst, row, col, v)                                            \
    do {                                                                     \
        float4 _w;                                                           \
        _w.x = __uint_as_float(f2tf((v).x)); _w.y = __uint_as_float(f2tf((v).y)); \
        _w.z = __uint_as_float(f2tf((v).z)); _w.w = __uint_as_float(f2tf((v).w)); \
        *(float4*)&(dst)[(row) * ST_STRIDE + (col)] = _w;                    \
    } while (0)

    // Fill stage 0 with chunk 0 (both halves).
#pragma unroll
    for (int h = 0; h < 2; h++) {
        const int hc = h * 32;
        float4 ha = *(const float4*)(hp + hc);
        float4 hb = *(const float4*)(hp + hc + 32 * ND);
        float4 da = *(const float4*)(dp + hc);
        float4 db = *(const float4*)(dp + hc + 32 * ND);
        CVT_STS(AsBase, fr,      hc + fc, ha);
        CVT_STS(AsBase, fr + 32, hc + fc, hb);
        CVT_STS(BsBase, fr,      hc + fc, da);
        CVT_STS(BsBase, fr + 32, hc + fc, db);
    }
    __syncthreads();

#define MMA_QUAD(Ac, Bc, ub, kcb)                                            \
    do {                                                                     \
        _Pragma("unroll")                                                    \
        for (int kt = 0; kt < 4; kt++) {                                     \
            const int kc = (kcb) + kt * 8 + tig;                             \
            uint32_t a[2][4];                                                \
            _Pragma("unroll")                                                \
            for (int mt = 0; mt < 2; mt++) {                                 \
                const int rb = wm * 32 + mt * 16 + gid;                      \
                a[mt][0] = __float_as_uint((Ac)[rb * ST_STRIDE + kc]);       \
                a[mt][1] = __float_as_uint((Ac)[(rb + 8) * ST_STRIDE + kc]); \
                a[mt][2] = __float_as_uint((Ac)[rb * ST_STRIDE + kc + 4]);   \
                a[mt][3] = __float_as_uint((Ac)[(rb + 8) * ST_STRIDE + kc + 4]); \
            }                                                                \
            float bf[2][2];                                                  \
            _Pragma("unroll")                                                \
            for (int nt = 0; nt < 2; nt++) {                                 \
                const int cb = wn * 16 + nt * 8 + gid;                       \
                bf[nt][0] = (Bc)[cb * ST_STRIDE + kc];                       \
                bf[nt][1] = (Bc)[cb * ST_STRIDE + kc + 4];                   \
            }                                                                \
            _Pragma("unroll")                                                \
            for (int l = 0; l < LT; l++) {                                   \
                const float u0 = (ub)[l * ND + (kcb) + kt * 8 + tig];        \
                const float u1 = (ub)[l * ND + (kcb) + kt * 8 + tig + 4];    \
                _Pragma("unroll")                                            \
                for (int nt = 0; nt < 2; nt++) {                             \
                    const uint32_t b0 = __float_as_uint(bf[nt][0] * u0);     \
                    const uint32_t b1 = __float_as_uint(bf[nt][1] * u1);     \
                    mma_tf32(acc[l][0][nt], a[0], b0, b1);                   \
                    mma_tf32(acc[l][1][nt], a[1], b0, b1);                   \
                }                                                            \
            }                                                                \
        }                                                                    \
    } while (0)

    for (int ch = 0; ch < NCH; ch++) {
        const int cur = ch & 1;
        const int k0 = ch * BK;
        const bool more = (ch < NCH - 1);

        const float* Ac = AsBase + cur * ST_FLOATS;
        const float* Bc = BsBase + cur * ST_FLOATS;
        float* An = AsBase + (cur ^ 1) * ST_FLOATS;
        float* Bn = BsBase + (cur ^ 1) * ST_FLOATS;
        const float* ub = Us + k0;

        // LDG half0 of next chunk; hidden under kt0-3 MMAs.
        float4 ha, hb, da, db;
        if (more) {
            ha = *(const float4*)(hp + k0 + BK);
            hb = *(const float4*)(hp + k0 + BK + 32 * ND);
            da = *(const float4*)(dp + k0 + BK);
            db = *(const float4*)(dp + k0 + BK + 32 * ND);
        }

        MMA_QUAD(Ac, Bc, ub, 0);

        if (more) {
            CVT_STS(An, fr,      fc, ha);
            CVT_STS(An, fr + 32, fc, hb);
            CVT_STS(Bn, fr,      fc, da);
            CVT_STS(Bn, fr + 32, fc, db);
            // LDG half1; hidden under kt4-7 MMAs.
            ha = *(const float4*)(hp + k0 + BK + 32);
            hb = *(const float4*)(hp + k0 + BK + 32 + 32 * ND);
            da = *(const float4*)(dp + k0 + BK + 32);
            db = *(const float4*)(dp + k0 + BK + 32 + 32 * ND);
        }

        MMA_QUAD(Ac, Bc, ub, 32);

        if (more) {
            CVT_STS(An, fr,      32 + fc, ha);
            CVT_STS(An, fr + 32, 32 + fc, hb);
            CVT_STS(Bn, fr,      32 + fc, da);
            CVT_STS(Bn, fr + 32, 32 + fc, db);
            __syncthreads();   // one barrier per 64-wide chunk
        }
    }

    // Epilogue: + rowadd[b,l,i] + coladd[b,l,o]  (bias folded into rowadd).
#pragma unroll
    for (int l = 0; l < LT; l++) {
        const int lg = l0 + l;
        const float* radd = &g_rowadd[((size_t)(b * NL + lg)) * NS + i0];
        const float* cadd = &g_coladd[((size_t)(b * NL + lg)) * NS + o0];
        float* op = out + (((size_t)(b * NL + lg)) * NS + i0) * NS + o0;
#pragma unroll
        for (int mt = 0; mt < 2; mt++) {
            const int r0 = wm * 32 + mt * 16 + gid;
            const float ra0 = radd[r0];
            const float ra1 = radd[r0 + 8];
#pragma unroll
            for (int nt = 0; nt < 2; nt++) {
                const int c = wn * 16 + nt * 8 + 2 * tig;
                const float2 ca = *(const float2*)&cadd[c];
                float2 v0, v1;
                v0.x = acc[l][mt][nt][0] + ra0 + ca.x;
                v0.y = acc[l][mt][nt][1] + ra0 + ca.y;
                v1.x = acc[l][mt][nt][2] + ra1 + ca.x;
                v1.y = acc[l][mt][nt][3] + ra1 + ca.y;
                *(float2*)&op[(size_t)r0 * NS + c]       = v0;
                *(float2*)&op[(size_t)(r0 + 8) * NS + c] = v1;
            }
        }
    }
}

extern "C" void kernel_launch(void* const* d_in, const int* in_sizes, int n_in,
                              void* d_out, int out_size) {
    const float* head = (const float*)d_in[0];
    const float* dep  = (const float*)d_in[1];
    const float* U    = (const float*)d_in[2];
    const float* W    = (const float*)d_in[3];
    const float* bias = (const float*)d_in[4];
    float* out = (float*)d_out;

    cudaFuncSetAttribute(biaffine_main_kernel,
                         cudaFuncAttributeMaxDynamicSharedMemorySize, SMEM_BYTES);

    stage1_kernel<<<dim3(NB * (NS / 32), 2), 256>>>(head, dep, W, bias);
    biaffine_main_kernel<<<dim3(NS / BN, NS / BM, NB * (NL / LT)), 256, SMEM_BYTES>>>(
        head, dep, U, out);
}